// round 12
// baseline (speedup 1.0000x reference)
#include <cuda_runtime.h>
#include <mma.h>
#include <cstdint>
#include <math.h>
using namespace nvcuda;

#define BATCH 64
#define C 128
#define HW 3136
#define KSPLIT 7
#define KPART 448        // HW / KSPLIT
#define NCHUNK 14        // KPART / 32
#define NUM_ITER 5
#define TRIU 8256
#define XTLD 130         // SYRK transposed-chunk ld (stride 2 banks)
#define MLD 130          // NS master ld (stride 2 banks)
#define SYTHR 384        // 12 warps x 3 tiles = 36
#define NSTHR 384        // 12 warps x 3 tiles = 36

__device__ float g_G[KSPLIT][BATCH][C][C];
__device__ float g_s[KSPLIT][BATCH][C];
__device__ float g_Gt[BATCH][TRIU];     // reduced Gram, triu-linear

// 36 upper-tri tiles over 12 warps x 3 slots (sorted by ti for A reuse)
__constant__ int8_t s_TI[12][3] = {
    {0,0,0}, {0,0,0}, {0,0,1}, {1,1,1}, {1,1,1}, {2,2,2},
    {2,2,2}, {3,3,3}, {3,3,4}, {4,4,4}, {5,5,5}, {6,6,7}};
__constant__ int8_t s_TJ[12][3] = {
    {0,1,2}, {3,4,5}, {6,7,1}, {2,3,4}, {5,6,7}, {2,3,4},
    {5,6,7}, {3,4,5}, {6,7,4}, {5,6,7}, {5,6,7}, {6,7,7}};

__device__ __forceinline__ float rtf32(float f) {
    uint32_t u; asm("cvt.rna.tf32.f32 %0, %1;" : "=r"(u) : "f"(f));
    return __uint_as_float(u);
}

// decode linear triu pos -> (i, j)
__device__ __forceinline__ void triu_ij(int pos, int& i, int& j) {
    i = (int)((257.0f - sqrtf(66049.0f - 8.0f * (float)pos)) * 0.5f);
    if (i < 0) i = 0;
    if (i > 127) i = 127;
    while (i > 0 && i * (257 - i) / 2 > pos) i--;
    while (i < 127 && (i + 1) * (257 - (i + 1)) / 2 <= pos) i++;
    j = i + (pos - i * (257 - i) / 2);
}

typedef wmma::fragment<wmma::accumulator, 16, 16, 8, float> AccFrag;
typedef wmma::fragment<wmma::matrix_a, 16, 16, 8, wmma::precision::tf32, wmma::row_major> AFragR;
typedef wmma::fragment<wmma::matrix_a, 16, 16, 8, wmma::precision::tf32, wmma::col_major> AFragC;
typedef wmma::fragment<wmma::matrix_b, 16, 16, 8, wmma::precision::tf32, wmma::row_major> BFragR;

// ===================== Kernel 1: SYRK via wmma tf32 =========================
// grid (KSPLIT, BATCH), 384 threads / 12 warps x 3 tiles. Threads <256 load.
__global__ __launch_bounds__(SYTHR, 2)
void syrk_tc(const float* __restrict__ x) {
    __shared__ __align__(16) float Xt[2][32 * XTLD];
    const int ks = blockIdx.x, b = blockIdx.y;
    const int t = threadIdx.x, w = t >> 5;
    const float* xb = x + (size_t)b * C * HW + (size_t)ks * KPART;

    int ti[3], tj[3];
#pragma unroll
    for (int s = 0; s < 3; s++) { ti[s] = s_TI[w][s]; tj[s] = s_TJ[w][s]; }

    AccFrag acc[3];
#pragma unroll
    for (int s = 0; s < 3; s++) wmma::fill_fragment(acc[s], 0.0f);

    const bool ldr = (t < 256);
    const int r0 = t >> 3, seg = t & 7;     // valid when ldr
    float4 R[4];
    float rs[4] = {0.f, 0.f, 0.f, 0.f};
    if (ldr) {
#pragma unroll
        for (int q = 0; q < 4; q++)
            R[q] = *(const float4*)(xb + (size_t)(r0 + q * 32) * HW + seg * 4);
    }

    for (int c = 0; c < NCHUNK; c++) {
        float* buf = Xt[c & 1];
        if (ldr) {
#pragma unroll
            for (int q = 0; q < 4; q++) {
                const float4 v = R[q];
                rs[q] += v.x + v.y + v.z + v.w;
                const int col = r0 + q * 32;
                buf[(seg * 4 + 0) * XTLD + col] = rtf32(v.x);
                buf[(seg * 4 + 1) * XTLD + col] = rtf32(v.y);
                buf[(seg * 4 + 2) * XTLD + col] = rtf32(v.z);
                buf[(seg * 4 + 3) * XTLD + col] = rtf32(v.w);
            }
            if (c + 1 < NCHUNK) {
                const float* xc = xb + (c + 1) * 32 + seg * 4;
#pragma unroll
                for (int q = 0; q < 4; q++)
                    R[q] = *(const float4*)(xc + (size_t)(r0 + q * 32) * HW);
            }
        }
        __syncthreads();
#pragma unroll
        for (int kk0 = 0; kk0 < 32; kk0 += 8) {
            const float* kbase = buf + kk0 * XTLD;
            AFragC a; BFragR bf;
#pragma unroll
            for (int s = 0; s < 3; s++) {
                if (s == 0 || ti[s] != ti[s - 1])
                    wmma::load_matrix_sync(a, kbase + ti[s] * 16, XTLD);
                wmma::load_matrix_sync(bf, kbase + tj[s] * 16, XTLD);
                wmma::mma_sync(acc[s], a, bf, acc[s]);
            }
        }
    }

    float* Gp = &g_G[ks][b][0][0];
#pragma unroll
    for (int s = 0; s < 3; s++)
        wmma::store_matrix_sync(Gp + ti[s] * 16 * C + tj[s] * 16, acc[s], C, wmma::mem_row_major);

    if (ldr) {
#pragma unroll
        for (int q = 0; q < 4; q++) {
            rs[q] += __shfl_xor_sync(0xffffffffu, rs[q], 1);
            rs[q] += __shfl_xor_sync(0xffffffffu, rs[q], 2);
            rs[q] += __shfl_xor_sync(0xffffffffu, rs[q], 4);
        }
        if (seg == 0) {
#pragma unroll
            for (int q = 0; q < 4; q++) g_s[ks][b][r0 + q * 32] = rs[q];
        }
    }
}

// ===================== Kernel 1b: reduce partials to triu-linear ============
// grid (33, BATCH), 256 threads. Full-chip width; coalesced in/out.
__global__ __launch_bounds__(256)
void reduce_g() {
    const int b = blockIdx.y;
    const int pos = blockIdx.x * 256 + threadIdx.x;
    if (pos >= TRIU) return;
    int i, j;
    triu_ij(pos, i, j);
    float g = 0.f;
#pragma unroll
    for (int p = 0; p < KSPLIT; p++) g += g_G[p][b][i][j];
    g_Gt[b][pos] = g;
}

// ===================== Kernel 2: fused Newton-Schulz ========================
// grid (BATCH), 384 threads / 12 warps x 3 tiles; shared-B phase 2.
#define NS_FLOATS (3 * 128 * MLD + 128 + 16)

__global__ __launch_bounds__(NSTHR, 1)
void ns_tc(float* __restrict__ out) {
    extern __shared__ __align__(16) float sm[];
    float* Y  = sm;
    float* Z  = Y + 128 * MLD;
    float* T  = Z + 128 * MLD;
    float* mu = T + 128 * MLD;
    float* red = mu + 128;

    const int b = blockIdx.x;
    const int t = threadIdx.x, w = t >> 5, lane = t & 31;

    int ti[3], tj[3];
#pragma unroll
    for (int s = 0; s < 3; s++) { ti[s] = s_TI[w][s]; tj[s] = s_TJ[w][s]; }

    // ---- prologue: mean, trace, Y0 = rna(sigma/tr) ----
    const float invn = 1.0f / (float)HW;
    const float* Gt = &g_Gt[b][0];

    if (t < 128) {
        float s = 0.f;
#pragma unroll
        for (int p = 0; p < KSPLIT; p++) s += g_s[p][b][t];
        mu[t] = s * invn;
    }
    __syncthreads();
    float dsum = 0.f;
    if (t < 128) {
        const float g = Gt[t * (257 - t) / 2];   // diag, triu-linear
        const float m = mu[t];
        dsum = g * invn - m * m;
    }
#pragma unroll
    for (int o = 16; o; o >>= 1) dsum += __shfl_down_sync(0xffffffffu, dsum, o);
    if (t < 128 && lane == 0) red[w] = dsum;
    __syncthreads();
    const float tr = red[0] + red[1] + red[2] + red[3];
    const float invtr = 1.0f / tr;

    // Y0 from triu-linear reduced Gram; mirror into smem.
    for (int pos = t; pos < TRIU; pos += NSTHR) {
        int i, j;
        triu_ij(pos, i, j);
        const float g = Gt[pos];
        const float y0 = rtf32((g * invn - mu[i] * mu[j]) * invtr);
        Y[i * MLD + j] = y0;
        Y[j * MLD + i] = y0;
    }
    __syncthreads();

    for (int it = 0; it < NUM_ITER; it++) {
        const bool lastit = (it == NUM_ITER - 1);
        const bool doZ = (it >= 1 && !lastit);

        if (it == 0) {
            // Z0 = I  =>  T0 = rna(1.5I - 0.5 Y0); Z1 = T0
            for (int e = t; e < C * C; e += NSTHR) {
                const int i = e >> 7, j = e & 127;
                const float v = rtf32(fmaf(-0.5f, Y[i * MLD + j], (i == j) ? 1.5f : 0.0f));
                T[i * MLD + j] = v;
                Z[i * MLD + j] = v;
            }
            __syncthreads();
        } else {
            // ---- phase 1: T = rna(-0.5 * (Z @ Y)), then diag += 1.5 ----
            AccFrag a1[3];
#pragma unroll
            for (int s = 0; s < 3; s++) wmma::fill_fragment(a1[s], 0.0f);
#pragma unroll 4
            for (int k0 = 0; k0 < C; k0 += 8) {
                AFragR az; BFragR by;
#pragma unroll
                for (int s = 0; s < 3; s++) {
                    if (s == 0 || ti[s] != ti[s - 1])
                        wmma::load_matrix_sync(az, Z + ti[s] * 16 * MLD + k0, MLD);
                    wmma::load_matrix_sync(by, Y + k0 * MLD + tj[s] * 16, MLD);
                    wmma::mma_sync(a1[s], az, by, a1[s]);
                }
            }
#pragma unroll
            for (int s = 0; s < 3; s++) {
#pragma unroll
                for (int e = 0; e < a1[s].num_elements; e++)
                    a1[s].x[e] = rtf32(-0.5f * a1[s].x[e]);
                wmma::store_matrix_sync(T + ti[s] * 16 * MLD + tj[s] * 16, a1[s], MLD, wmma::mem_row_major);
                if (tj[s] > ti[s])
                    wmma::store_matrix_sync(T + tj[s] * 16 * MLD + ti[s] * 16, a1[s], MLD, wmma::mem_col_major);
            }
            __syncthreads();
            if (t < 128) T[t * MLD + t] = rtf32(1.5f + T[t * MLD + t]);
            __syncthreads();
        }

        // ---- phase 2: Ynew = Y@T ; Znew = sym(Z@T) -- shared B fragment ----
        {
            AccFrag a2[3], a3[3];
#pragma unroll
            for (int s = 0; s < 3; s++) { wmma::fill_fragment(a2[s], 0.0f); wmma::fill_fragment(a3[s], 0.0f); }
#pragma unroll 4
            for (int k0 = 0; k0 < C; k0 += 8) {
                AFragR ay, az; BFragR bt;
#pragma unroll
                for (int s = 0; s < 3; s++) {
                    if (s == 0 || ti[s] != ti[s - 1]) {
                        wmma::load_matrix_sync(ay, Y + ti[s] * 16 * MLD + k0, MLD);
                        if (doZ)
                            wmma::load_matrix_sync(az, Z + ti[s] * 16 * MLD + k0, MLD);
                    }
                    wmma::load_matrix_sync(bt, T + k0 * MLD + tj[s] * 16, MLD);
                    wmma::mma_sync(a2[s], ay, bt, a2[s]);
                    if (doZ)
                        wmma::mma_sync(a3[s], az, bt, a3[s]);
                }
            }
            __syncthreads();   // all reads of Y/Z complete before overwrite
            if (!lastit) {
#pragma unroll
                for (int s = 0; s < 3; s++)
#pragma unroll
                    for (int e = 0; e < a2[s].num_elements; e++) {
                        a2[s].x[e] = rtf32(a2[s].x[e]);
                        a3[s].x[e] = rtf32(a3[s].x[e]);
                    }
            }
#pragma unroll
            for (int s = 0; s < 3; s++) {
                wmma::store_matrix_sync(Y + ti[s] * 16 * MLD + tj[s] * 16, a2[s], MLD, wmma::mem_row_major);
                if (tj[s] > ti[s])
                    wmma::store_matrix_sync(Y + tj[s] * 16 * MLD + ti[s] * 16, a2[s], MLD, wmma::mem_col_major);
                if (doZ) {
                    wmma::store_matrix_sync(Z + ti[s] * 16 * MLD + tj[s] * 16, a3[s], MLD, wmma::mem_row_major);
                    if (tj[s] > ti[s])
                        wmma::store_matrix_sync(Z + tj[s] * 16 * MLD + ti[s] * 16, a3[s], MLD, wmma::mem_col_major);
                }
            }
        }
        __syncthreads();
    }

    // ---- output: triu(Y * sqrt(tr)) ----
    const float s = sqrtf(tr);
    if (t < 128) {
        const int i = t;
        float* o = out + (size_t)b * TRIU + i * (257 - i) / 2;
        const float* yr = Y + i * MLD;
        for (int j = i; j < C; j++) o[j - i] = yr[j] * s;
    }
}

// =================== launch ==================================================
extern "C" void kernel_launch(void* const* d_in, const int* in_sizes, int n_in,
                              void* d_out, int out_size) {
    const float* x = (const float*)d_in[0];
    float* out = (float*)d_out;
    cudaFuncSetAttribute(ns_tc, cudaFuncAttributeMaxDynamicSharedMemorySize,
                         NS_FLOATS * (int)sizeof(float));
    dim3 g1(KSPLIT, BATCH);
    syrk_tc<<<g1, SYTHR>>>(x);
    dim3 g2(33, BATCH);
    reduce_g<<<g2, 256>>>();
    ns_tc<<<BATCH, NSTHR, NS_FLOATS * sizeof(float)>>>(out);
}

// round 13
// speedup vs baseline: 1.1783x; 1.1783x over previous
#include <cuda_runtime.h>
#include <mma.h>
#include <cstdint>
#include <math.h>
using namespace nvcuda;

#define BATCH 64
#define C 128
#define HW 3136
#define KSPLIT 7
#define KPART 448        // HW / KSPLIT
#define NCHUNK 14        // KPART / 32
#define NUM_ITER 5
#define TRIU 8256
#define XTLD 132         // SYRK transposed-chunk ld (measured best)
#define MLD 132          // NS master ld (measured best)
#define SYTHR 384        // 12 warps x 3 tiles = 36
#define NSTHR 384        // 12 warps x 3 tiles = 36

__device__ float g_G[KSPLIT][BATCH][C][C];
__device__ float g_s[KSPLIT][BATCH][C];
__device__ float g_Gt[BATCH][TRIU];     // reduced Gram, triu-linear

// 36 upper-tri tiles over 12 warps x 3 slots (sorted by ti for A reuse)
__constant__ int8_t s_TI[12][3] = {
    {0,0,0}, {0,0,0}, {0,0,1}, {1,1,1}, {1,1,1}, {2,2,2},
    {2,2,2}, {3,3,3}, {3,3,4}, {4,4,4}, {5,5,5}, {6,6,7}};
__constant__ int8_t s_TJ[12][3] = {
    {0,1,2}, {3,4,5}, {6,7,1}, {2,3,4}, {5,6,7}, {2,3,4},
    {5,6,7}, {3,4,5}, {6,7,4}, {5,6,7}, {5,6,7}, {6,7,7}};

__device__ __forceinline__ float rtf32(float f) {
    uint32_t u; asm("cvt.rna.tf32.f32 %0, %1;" : "=r"(u) : "f"(f));
    return __uint_as_float(u);
}

// decode linear triu pos -> (i, j)
__device__ __forceinline__ void triu_ij(int pos, int& i, int& j) {
    i = (int)((257.0f - sqrtf(66049.0f - 8.0f * (float)pos)) * 0.5f);
    if (i < 0) i = 0;
    if (i > 127) i = 127;
    while (i > 0 && i * (257 - i) / 2 > pos) i--;
    while (i < 127 && (i + 1) * (257 - (i + 1)) / 2 <= pos) i++;
    j = i + (pos - i * (257 - i) / 2);
}

typedef wmma::fragment<wmma::accumulator, 16, 16, 8, float> AccFrag;
typedef wmma::fragment<wmma::matrix_a, 16, 16, 8, wmma::precision::tf32, wmma::row_major> AFragR;
typedef wmma::fragment<wmma::matrix_a, 16, 16, 8, wmma::precision::tf32, wmma::col_major> AFragC;
typedef wmma::fragment<wmma::matrix_b, 16, 16, 8, wmma::precision::tf32, wmma::row_major> BFragR;

// ===================== Kernel 1: SYRK via wmma tf32 =========================
// grid (KSPLIT, BATCH), 384 threads / 12 warps x 3 tiles. Threads <256 load.
__global__ __launch_bounds__(SYTHR, 2)
void syrk_tc(const float* __restrict__ x) {
    __shared__ __align__(16) float Xt[2][32 * XTLD];
    const int ks = blockIdx.x, b = blockIdx.y;
    const int t = threadIdx.x, w = t >> 5;
    const float* xb = x + (size_t)b * C * HW + (size_t)ks * KPART;

    int ti[3], tj[3];
#pragma unroll
    for (int s = 0; s < 3; s++) { ti[s] = s_TI[w][s]; tj[s] = s_TJ[w][s]; }

    AccFrag acc[3];
#pragma unroll
    for (int s = 0; s < 3; s++) wmma::fill_fragment(acc[s], 0.0f);

    const bool ldr = (t < 256);
    const int r0 = t >> 3, seg = t & 7;     // valid when ldr
    float4 R[4];
    float rs[4] = {0.f, 0.f, 0.f, 0.f};
    if (ldr) {
#pragma unroll
        for (int q = 0; q < 4; q++)
            R[q] = *(const float4*)(xb + (size_t)(r0 + q * 32) * HW + seg * 4);
    }

    for (int c = 0; c < NCHUNK; c++) {
        float* buf = Xt[c & 1];
        if (ldr) {
#pragma unroll
            for (int q = 0; q < 4; q++) {
                const float4 v = R[q];
                rs[q] += v.x + v.y + v.z + v.w;
                const int col = r0 + q * 32;
                buf[(seg * 4 + 0) * XTLD + col] = rtf32(v.x);
                buf[(seg * 4 + 1) * XTLD + col] = rtf32(v.y);
                buf[(seg * 4 + 2) * XTLD + col] = rtf32(v.z);
                buf[(seg * 4 + 3) * XTLD + col] = rtf32(v.w);
            }
            if (c + 1 < NCHUNK) {
                const float* xc = xb + (c + 1) * 32 + seg * 4;
#pragma unroll
                for (int q = 0; q < 4; q++)
                    R[q] = *(const float4*)(xc + (size_t)(r0 + q * 32) * HW);
            }
        }
        __syncthreads();
#pragma unroll
        for (int kk0 = 0; kk0 < 32; kk0 += 8) {
            const float* kbase = buf + kk0 * XTLD;
            AFragC a; BFragR bf;
#pragma unroll
            for (int s = 0; s < 3; s++) {
                if (s == 0 || ti[s] != ti[s - 1])
                    wmma::load_matrix_sync(a, kbase + ti[s] * 16, XTLD);
                wmma::load_matrix_sync(bf, kbase + tj[s] * 16, XTLD);
                wmma::mma_sync(acc[s], a, bf, acc[s]);
            }
        }
    }

    float* Gp = &g_G[ks][b][0][0];
#pragma unroll
    for (int s = 0; s < 3; s++)
        wmma::store_matrix_sync(Gp + ti[s] * 16 * C + tj[s] * 16, acc[s], C, wmma::mem_row_major);

    if (ldr) {
#pragma unroll
        for (int q = 0; q < 4; q++) {
            rs[q] += __shfl_xor_sync(0xffffffffu, rs[q], 1);
            rs[q] += __shfl_xor_sync(0xffffffffu, rs[q], 2);
            rs[q] += __shfl_xor_sync(0xffffffffu, rs[q], 4);
        }
        if (seg == 0) {
#pragma unroll
            for (int q = 0; q < 4; q++) g_s[ks][b][r0 + q * 32] = rs[q];
        }
    }
}

// ===================== Kernel 1b: reduce partials to triu-linear ============
// grid (33, BATCH), 256 threads. Full-chip width; coalesced in/out.
__global__ __launch_bounds__(256)
void reduce_g() {
    const int b = blockIdx.y;
    const int pos = blockIdx.x * 256 + threadIdx.x;
    if (pos >= TRIU) return;
    int i, j;
    triu_ij(pos, i, j);
    float g = 0.f;
#pragma unroll
    for (int p = 0; p < KSPLIT; p++) g += g_G[p][b][i][j];
    g_Gt[b][pos] = g;
}

// ===================== Kernel 2: fused Newton-Schulz ========================
// grid (BATCH), 384 threads / 12 warps x 3 tiles; shared-B phase 2.
#define NS_FLOATS (3 * 128 * MLD + 128 + 16)

__global__ __launch_bounds__(NSTHR, 1)
void ns_tc(float* __restrict__ out) {
    extern __shared__ __align__(16) float sm[];
    float* Y  = sm;
    float* Z  = Y + 128 * MLD;
    float* T  = Z + 128 * MLD;
    float* mu = T + 128 * MLD;
    float* red = mu + 128;

    const int b = blockIdx.x;
    const int t = threadIdx.x, w = t >> 5, lane = t & 31;

    int ti[3], tj[3];
#pragma unroll
    for (int s = 0; s < 3; s++) { ti[s] = s_TI[w][s]; tj[s] = s_TJ[w][s]; }

    // ---- prologue: mean, trace, Y0 = rna(sigma/tr) ----
    const float invn = 1.0f / (float)HW;
    const float* Gt = &g_Gt[b][0];

    if (t < 128) {
        float s = 0.f;
#pragma unroll
        for (int p = 0; p < KSPLIT; p++) s += g_s[p][b][t];
        mu[t] = s * invn;
    }
    __syncthreads();
    float dsum = 0.f;
    if (t < 128) {
        const float g = Gt[t * (257 - t) / 2];   // diag, triu-linear
        const float m = mu[t];
        dsum = g * invn - m * m;
    }
#pragma unroll
    for (int o = 16; o; o >>= 1) dsum += __shfl_down_sync(0xffffffffu, dsum, o);
    if (t < 128 && lane == 0) red[w] = dsum;
    __syncthreads();
    const float tr = red[0] + red[1] + red[2] + red[3];
    const float invtr = 1.0f / tr;

    // Y0 from triu-linear reduced Gram; mirror into smem.
    for (int pos = t; pos < TRIU; pos += NSTHR) {
        int i, j;
        triu_ij(pos, i, j);
        const float g = Gt[pos];
        const float y0 = rtf32((g * invn - mu[i] * mu[j]) * invtr);
        Y[i * MLD + j] = y0;
        Y[j * MLD + i] = y0;
    }
    __syncthreads();

    for (int it = 0; it < NUM_ITER; it++) {
        const bool lastit = (it == NUM_ITER - 1);
        const bool doZ = (it >= 1 && !lastit);

        if (it == 0) {
            // Z0 = I  =>  T0 = rna(1.5I - 0.5 Y0); Z1 = T0
            for (int e = t; e < C * C; e += NSTHR) {
                const int i = e >> 7, j = e & 127;
                const float v = rtf32(fmaf(-0.5f, Y[i * MLD + j], (i == j) ? 1.5f : 0.0f));
                T[i * MLD + j] = v;
                Z[i * MLD + j] = v;
            }
            __syncthreads();
        } else {
            // ---- phase 1: T = rna(-0.5 * (Z @ Y)), then diag += 1.5 ----
            AccFrag a1[3];
#pragma unroll
            for (int s = 0; s < 3; s++) wmma::fill_fragment(a1[s], 0.0f);
#pragma unroll 4
            for (int k0 = 0; k0 < C; k0 += 8) {
                AFragR az; BFragR by;
#pragma unroll
                for (int s = 0; s < 3; s++) {
                    if (s == 0 || ti[s] != ti[s - 1])
                        wmma::load_matrix_sync(az, Z + ti[s] * 16 * MLD + k0, MLD);
                    wmma::load_matrix_sync(by, Y + k0 * MLD + tj[s] * 16, MLD);
                    wmma::mma_sync(a1[s], az, by, a1[s]);
                }
            }
#pragma unroll
            for (int s = 0; s < 3; s++) {
#pragma unroll
                for (int e = 0; e < a1[s].num_elements; e++)
                    a1[s].x[e] = rtf32(-0.5f * a1[s].x[e]);
                wmma::store_matrix_sync(T + ti[s] * 16 * MLD + tj[s] * 16, a1[s], MLD, wmma::mem_row_major);
                if (tj[s] > ti[s])
                    wmma::store_matrix_sync(T + tj[s] * 16 * MLD + ti[s] * 16, a1[s], MLD, wmma::mem_col_major);
            }
            __syncthreads();
            if (t < 128) T[t * MLD + t] = rtf32(1.5f + T[t * MLD + t]);
            __syncthreads();
        }

        // ---- phase 2: Ynew = Y@T ; Znew = sym(Z@T) -- shared B fragment ----
        {
            AccFrag a2[3], a3[3];
#pragma unroll
            for (int s = 0; s < 3; s++) { wmma::fill_fragment(a2[s], 0.0f); wmma::fill_fragment(a3[s], 0.0f); }
#pragma unroll 4
            for (int k0 = 0; k0 < C; k0 += 8) {
                AFragR ay, az; BFragR bt;
#pragma unroll
                for (int s = 0; s < 3; s++) {
                    if (s == 0 || ti[s] != ti[s - 1]) {
                        wmma::load_matrix_sync(ay, Y + ti[s] * 16 * MLD + k0, MLD);
                        if (doZ)
                            wmma::load_matrix_sync(az, Z + ti[s] * 16 * MLD + k0, MLD);
                    }
                    wmma::load_matrix_sync(bt, T + k0 * MLD + tj[s] * 16, MLD);
                    wmma::mma_sync(a2[s], ay, bt, a2[s]);
                    if (doZ)
                        wmma::mma_sync(a3[s], az, bt, a3[s]);
                }
            }
            __syncthreads();   // all reads of Y/Z complete before overwrite
            if (!lastit) {
#pragma unroll
                for (int s = 0; s < 3; s++)
#pragma unroll
                    for (int e = 0; e < a2[s].num_elements; e++) {
                        a2[s].x[e] = rtf32(a2[s].x[e]);
                        a3[s].x[e] = rtf32(a3[s].x[e]);
                    }
            }
#pragma unroll
            for (int s = 0; s < 3; s++) {
                wmma::store_matrix_sync(Y + ti[s] * 16 * MLD + tj[s] * 16, a2[s], MLD, wmma::mem_row_major);
                if (tj[s] > ti[s])
                    wmma::store_matrix_sync(Y + tj[s] * 16 * MLD + ti[s] * 16, a2[s], MLD, wmma::mem_col_major);
                if (doZ) {
                    wmma::store_matrix_sync(Z + ti[s] * 16 * MLD + tj[s] * 16, a3[s], MLD, wmma::mem_row_major);
                    if (tj[s] > ti[s])
                        wmma::store_matrix_sync(Z + tj[s] * 16 * MLD + ti[s] * 16, a3[s], MLD, wmma::mem_col_major);
                }
            }
        }
        __syncthreads();
    }

    // ---- output: triu(Y * sqrt(tr)) ----
    const float s = sqrtf(tr);
    if (t < 128) {
        const int i = t;
        float* o = out + (size_t)b * TRIU + i * (257 - i) / 2;
        const float* yr = Y + i * MLD;
        for (int j = i; j < C; j++) o[j - i] = yr[j] * s;
    }
}

// =================== launch ==================================================
extern "C" void kernel_launch(void* const* d_in, const int* in_sizes, int n_in,
                              void* d_out, int out_size) {
    const float* x = (const float*)d_in[0];
    float* out = (float*)d_out;
    cudaFuncSetAttribute(ns_tc, cudaFuncAttributeMaxDynamicSharedMemorySize,
                         NS_FLOATS * (int)sizeof(float));
    dim3 g1(KSPLIT, BATCH);
    syrk_tc<<<g1, SYTHR>>>(x);
    dim3 g2(33, BATCH);
    reduce_g<<<g2, 256>>>();
    ns_tc<<<BATCH, NSTHR, NS_FLOATS * sizeof(float)>>>(out);
}

// round 14
// speedup vs baseline: 1.2521x; 1.0627x over previous
#include <cuda_runtime.h>
#include <mma.h>
#include <cstdint>
#include <math.h>
using namespace nvcuda;

#define BATCH 64
#define C 128
#define HW 3136
#define KSPLIT 7
#define KPART 448        // HW / KSPLIT
#define NCHUNK 14        // KPART / 32
#define NUM_ITER 5
#define TRIU 8256
#define XTLD 132         // SYRK transposed-chunk ld (measured best)
#define MLD 132          // NS master ld (measured best)
#define SYTHR 320        // 10 warps x 1 super-tile
#define NSTHR 320        // 10 warps x 1 super-tile

__device__ float g_G[KSPLIT][BATCH][C][C];
__device__ float g_s[KSPLIT][BATCH][C];
__device__ float g_Gt[BATCH][TRIU];     // reduced Gram, triu-linear

// 10 super-tiles (2x2 blocks of 16x16 tiles) covering the 8x8 upper triangle:
// warps 0-5: full off-diagonal blocks; warps 6-9: diagonal blocks (3 tiles).
__constant__ int8_t u_SI[10] = {0,0,0,1,1,2, 0,1,2,3};
__constant__ int8_t u_SJ[10] = {1,2,3,2,3,3, 0,1,2,3};

__device__ __forceinline__ float rtf32(float f) {
    uint32_t u; asm("cvt.rna.tf32.f32 %0, %1;" : "=r"(u) : "f"(f));
    return __uint_as_float(u);
}

// decode linear triu pos -> (i, j)
__device__ __forceinline__ void triu_ij(int pos, int& i, int& j) {
    i = (int)((257.0f - sqrtf(66049.0f - 8.0f * (float)pos)) * 0.5f);
    if (i < 0) i = 0;
    if (i > 127) i = 127;
    while (i > 0 && i * (257 - i) / 2 > pos) i--;
    while (i < 127 && (i + 1) * (257 - (i + 1)) / 2 <= pos) i++;
    j = i + (pos - i * (257 - i) / 2);
}

typedef wmma::fragment<wmma::accumulator, 16, 16, 8, float> AccFrag;
typedef wmma::fragment<wmma::matrix_a, 16, 16, 8, wmma::precision::tf32, wmma::row_major> AFragR;
typedef wmma::fragment<wmma::matrix_a, 16, 16, 8, wmma::precision::tf32, wmma::col_major> AFragC;
typedef wmma::fragment<wmma::matrix_b, 16, 16, 8, wmma::precision::tf32, wmma::row_major> BFragR;

// ===================== Kernel 1: SYRK via wmma tf32 =========================
// grid (KSPLIT, BATCH), 320 threads / 10 warps x 2x2 super-tile.
__global__ __launch_bounds__(SYTHR, 2)
void syrk_tc(const float* __restrict__ x) {
    __shared__ __align__(16) float Xt[2][32 * XTLD];
    const int ks = blockIdx.x, b = blockIdx.y;
    const int t = threadIdx.x, w = t >> 5;
    const float* xb = x + (size_t)b * C * HW + (size_t)ks * KPART;

    const int ti0 = u_SI[w] * 2, tj0 = u_SJ[w] * 2;
    const bool diag = (w >= 6);

    AccFrag acc[4];
#pragma unroll
    for (int s = 0; s < 4; s++) wmma::fill_fragment(acc[s], 0.0f);

    const bool ldr = (t < 256);
    const int r0 = t >> 3, seg = t & 7;     // valid when ldr
    float4 R[4];
    float rs[4] = {0.f, 0.f, 0.f, 0.f};
    if (ldr) {
#pragma unroll
        for (int q = 0; q < 4; q++)
            R[q] = *(const float4*)(xb + (size_t)(r0 + q * 32) * HW + seg * 4);
    }

    for (int c = 0; c < NCHUNK; c++) {
        float* buf = Xt[c & 1];
        if (ldr) {
#pragma unroll
            for (int q = 0; q < 4; q++) {
                const float4 v = R[q];
                rs[q] += v.x + v.y + v.z + v.w;
                const int col = r0 + q * 32;
                buf[(seg * 4 + 0) * XTLD + col] = rtf32(v.x);
                buf[(seg * 4 + 1) * XTLD + col] = rtf32(v.y);
                buf[(seg * 4 + 2) * XTLD + col] = rtf32(v.z);
                buf[(seg * 4 + 3) * XTLD + col] = rtf32(v.w);
            }
            if (c + 1 < NCHUNK) {
                const float* xc = xb + (c + 1) * 32 + seg * 4;
#pragma unroll
                for (int q = 0; q < 4; q++)
                    R[q] = *(const float4*)(xc + (size_t)(r0 + q * 32) * HW);
            }
        }
        __syncthreads();
#pragma unroll
        for (int kk0 = 0; kk0 < 32; kk0 += 8) {
            const float* kbase = buf + kk0 * XTLD;
            AFragC a0, a1; BFragR b0, b1;
            wmma::load_matrix_sync(a0, kbase + ti0 * 16, XTLD);
            wmma::load_matrix_sync(a1, kbase + ti0 * 16 + 16, XTLD);
            wmma::load_matrix_sync(b0, kbase + tj0 * 16, XTLD);
            wmma::load_matrix_sync(b1, kbase + tj0 * 16 + 16, XTLD);
            wmma::mma_sync(acc[0], a0, b0, acc[0]);
            wmma::mma_sync(acc[1], a0, b1, acc[1]);
            if (!diag) wmma::mma_sync(acc[2], a1, b0, acc[2]);
            wmma::mma_sync(acc[3], a1, b1, acc[3]);
        }
    }

    float* Gp = &g_G[ks][b][0][0];
    wmma::store_matrix_sync(Gp + ti0 * 16 * C + tj0 * 16, acc[0], C, wmma::mem_row_major);
    wmma::store_matrix_sync(Gp + ti0 * 16 * C + (tj0 + 1) * 16, acc[1], C, wmma::mem_row_major);
    if (!diag)
        wmma::store_matrix_sync(Gp + (ti0 + 1) * 16 * C + tj0 * 16, acc[2], C, wmma::mem_row_major);
    wmma::store_matrix_sync(Gp + (ti0 + 1) * 16 * C + (tj0 + 1) * 16, acc[3], C, wmma::mem_row_major);

    if (ldr) {
#pragma unroll
        for (int q = 0; q < 4; q++) {
            rs[q] += __shfl_xor_sync(0xffffffffu, rs[q], 1);
            rs[q] += __shfl_xor_sync(0xffffffffu, rs[q], 2);
            rs[q] += __shfl_xor_sync(0xffffffffu, rs[q], 4);
        }
        if (seg == 0) {
#pragma unroll
            for (int q = 0; q < 4; q++) g_s[ks][b][r0 + q * 32] = rs[q];
        }
    }
}

// ===================== Kernel 1b: reduce partials to triu-linear ============
__global__ __launch_bounds__(256)
void reduce_g() {
    const int b = blockIdx.y;
    const int pos = blockIdx.x * 256 + threadIdx.x;
    if (pos >= TRIU) return;
    int i, j;
    triu_ij(pos, i, j);
    float g = 0.f;
#pragma unroll
    for (int p = 0; p < KSPLIT; p++) g += g_G[p][b][i][j];
    g_Gt[b][pos] = g;
}

// ===================== Kernel 2: fused Newton-Schulz ========================
// grid (BATCH), 320 threads / 10 warps x 2x2 super-tile; shared-B phase 2.
#define NS_FLOATS (3 * 128 * MLD + 128 + 16)

// store a tile (+mirror if above diagonal)
#define STORE_SYM(M, frag, a, bcol) do { \
        wmma::store_matrix_sync((M) + (a) * 16 * MLD + (bcol) * 16, (frag), MLD, wmma::mem_row_major); \
        if ((bcol) > (a)) \
            wmma::store_matrix_sync((M) + (bcol) * 16 * MLD + (a) * 16, (frag), MLD, wmma::mem_col_major); \
    } while (0)

__global__ __launch_bounds__(NSTHR, 1)
void ns_tc(float* __restrict__ out) {
    extern __shared__ __align__(16) float sm[];
    float* Y  = sm;
    float* Z  = Y + 128 * MLD;
    float* T  = Z + 128 * MLD;
    float* mu = T + 128 * MLD;
    float* red = mu + 128;

    const int b = blockIdx.x;
    const int t = threadIdx.x, w = t >> 5, lane = t & 31;

    const int ti0 = u_SI[w] * 2, tj0 = u_SJ[w] * 2;
    const bool diag = (w >= 6);

    // ---- prologue: mean, trace, Y0 = rna(sigma/tr) ----
    const float invn = 1.0f / (float)HW;
    const float* Gt = &g_Gt[b][0];

    if (t < 128) {
        float s = 0.f;
#pragma unroll
        for (int p = 0; p < KSPLIT; p++) s += g_s[p][b][t];
        mu[t] = s * invn;
    }
    __syncthreads();
    float dsum = 0.f;
    if (t < 128) {
        const float g = Gt[t * (257 - t) / 2];   // diag, triu-linear
        const float m = mu[t];
        dsum = g * invn - m * m;
    }
#pragma unroll
    for (int o = 16; o; o >>= 1) dsum += __shfl_down_sync(0xffffffffu, dsum, o);
    if (t < 128 && lane == 0) red[w] = dsum;
    __syncthreads();
    const float tr = red[0] + red[1] + red[2] + red[3];
    const float invtr = 1.0f / tr;

    // Y0 from triu-linear reduced Gram; mirror into smem.
    for (int pos = t; pos < TRIU; pos += NSTHR) {
        int i, j;
        triu_ij(pos, i, j);
        const float g = Gt[pos];
        const float y0 = rtf32((g * invn - mu[i] * mu[j]) * invtr);
        Y[i * MLD + j] = y0;
        Y[j * MLD + i] = y0;
    }
    __syncthreads();

    for (int it = 0; it < NUM_ITER; it++) {
        const bool lastit = (it == NUM_ITER - 1);
        const bool doZ = (it >= 1 && !lastit);

        if (it == 0) {
            // Z0 = I  =>  T0 = rna(1.5I - 0.5 Y0); Z1 = T0
            for (int e = t; e < C * C; e += NSTHR) {
                const int i = e >> 7, j = e & 127;
                const float v = rtf32(fmaf(-0.5f, Y[i * MLD + j], (i == j) ? 1.5f : 0.0f));
                T[i * MLD + j] = v;
                Z[i * MLD + j] = v;
            }
            __syncthreads();
        } else {
            // ---- phase 1: T = rna(-0.5 * (Z @ Y)), then diag += 1.5 ----
            AccFrag a1[4];
#pragma unroll
            for (int s = 0; s < 4; s++) wmma::fill_fragment(a1[s], 0.0f);
#pragma unroll 4
            for (int k0 = 0; k0 < C; k0 += 8) {
                AFragR az0, az1; BFragR by0, by1;
                wmma::load_matrix_sync(az0, Z + ti0 * 16 * MLD + k0, MLD);
                wmma::load_matrix_sync(az1, Z + (ti0 + 1) * 16 * MLD + k0, MLD);
                wmma::load_matrix_sync(by0, Y + k0 * MLD + tj0 * 16, MLD);
                wmma::load_matrix_sync(by1, Y + k0 * MLD + tj0 * 16 + 16, MLD);
                wmma::mma_sync(a1[0], az0, by0, a1[0]);
                wmma::mma_sync(a1[1], az0, by1, a1[1]);
                if (!diag) wmma::mma_sync(a1[2], az1, by0, a1[2]);
                wmma::mma_sync(a1[3], az1, by1, a1[3]);
            }
#pragma unroll
            for (int s = 0; s < 4; s++)
#pragma unroll
                for (int e = 0; e < a1[s].num_elements; e++)
                    a1[s].x[e] = rtf32(-0.5f * a1[s].x[e]);
            STORE_SYM(T, a1[0], ti0, tj0);
            STORE_SYM(T, a1[1], ti0, tj0 + 1);
            if (!diag) STORE_SYM(T, a1[2], ti0 + 1, tj0);
            STORE_SYM(T, a1[3], ti0 + 1, tj0 + 1);
            __syncthreads();
            if (t < 128) T[t * MLD + t] = rtf32(1.5f + T[t * MLD + t]);
            __syncthreads();
        }

        // ---- phase 2: Ynew = Y@T ; Znew = sym(Z@T) -- shared B fragments ----
        {
            AccFrag a2[4], a3[4];
#pragma unroll
            for (int s = 0; s < 4; s++) { wmma::fill_fragment(a2[s], 0.0f); wmma::fill_fragment(a3[s], 0.0f); }
#pragma unroll 4
            for (int k0 = 0; k0 < C; k0 += 8) {
                AFragR ay0, ay1, az0, az1; BFragR bt0, bt1;
                wmma::load_matrix_sync(ay0, Y + ti0 * 16 * MLD + k0, MLD);
                wmma::load_matrix_sync(ay1, Y + (ti0 + 1) * 16 * MLD + k0, MLD);
                wmma::load_matrix_sync(bt0, T + k0 * MLD + tj0 * 16, MLD);
                wmma::load_matrix_sync(bt1, T + k0 * MLD + tj0 * 16 + 16, MLD);
                wmma::mma_sync(a2[0], ay0, bt0, a2[0]);
                wmma::mma_sync(a2[1], ay0, bt1, a2[1]);
                if (!diag) wmma::mma_sync(a2[2], ay1, bt0, a2[2]);
                wmma::mma_sync(a2[3], ay1, bt1, a2[3]);
                if (doZ) {
                    wmma::load_matrix_sync(az0, Z + ti0 * 16 * MLD + k0, MLD);
                    wmma::load_matrix_sync(az1, Z + (ti0 + 1) * 16 * MLD + k0, MLD);
                    wmma::mma_sync(a3[0], az0, bt0, a3[0]);
                    wmma::mma_sync(a3[1], az0, bt1, a3[1]);
                    if (!diag) wmma::mma_sync(a3[2], az1, bt0, a3[2]);
                    wmma::mma_sync(a3[3], az1, bt1, a3[3]);
                }
            }
            __syncthreads();   // all reads of Y/Z complete before overwrite
            if (!lastit) {
#pragma unroll
                for (int s = 0; s < 4; s++)
#pragma unroll
                    for (int e = 0; e < a2[s].num_elements; e++) {
                        a2[s].x[e] = rtf32(a2[s].x[e]);
                        a3[s].x[e] = rtf32(a3[s].x[e]);
                    }
            }
            STORE_SYM(Y, a2[0], ti0, tj0);
            STORE_SYM(Y, a2[1], ti0, tj0 + 1);
            if (!diag) STORE_SYM(Y, a2[2], ti0 + 1, tj0);
            STORE_SYM(Y, a2[3], ti0 + 1, tj0 + 1);
            if (doZ) {
                STORE_SYM(Z, a3[0], ti0, tj0);
                STORE_SYM(Z, a3[1], ti0, tj0 + 1);
                if (!diag) STORE_SYM(Z, a3[2], ti0 + 1, tj0);
                STORE_SYM(Z, a3[3], ti0 + 1, tj0 + 1);
            }
        }
        __syncthreads();
    }

    // ---- output: triu(Y * sqrt(tr)) ----
    const float s = sqrtf(tr);
    if (t < 128) {
        const int i = t;
        float* o = out + (size_t)b * TRIU + i * (257 - i) / 2;
        const float* yr = Y + i * MLD;
        for (int j = i; j < C; j++) o[j - i] = yr[j] * s;
    }
}

// =================== launch ==================================================
extern "C" void kernel_launch(void* const* d_in, const int* in_sizes, int n_in,
                              void* d_out, int out_size) {
    const float* x = (const float*)d_in[0];
    float* out = (float*)d_out;
    cudaFuncSetAttribute(ns_tc, cudaFuncAttributeMaxDynamicSharedMemorySize,
                         NS_FLOATS * (int)sizeof(float));
    dim3 g1(KSPLIT, BATCH);
    syrk_tc<<<g1, SYTHR>>>(x);
    dim3 g2(33, BATCH);
    reduce_g<<<g2, 256>>>();
    ns_tc<<<BATCH, NSTHR, NS_FLOATS * sizeof(float)>>>(out);
}

// round 15
// speedup vs baseline: 1.2717x; 1.0156x over previous
#include <cuda_runtime.h>
#include <mma.h>
#include <cstdint>
#include <math.h>
using namespace nvcuda;

#define BATCH 64
#define C 128
#define HW 3136
#define KSPLIT 7
#define KPART 448        // HW / KSPLIT
#define NCHUNK 14        // KPART / 32
#define NUM_ITER 5
#define TRIU 8256
#define XTLD 132         // SYRK transposed-chunk ld (measured best)
#define MLD 132          // NS master ld (measured best)
#define SYTHR 320        // SYRK: 10 warps x 2x2 super-tile (measured best)
#define NSTHR 384        // NS: 12 warps x 3 tiles (measured best)

__device__ float g_G[KSPLIT][BATCH][C][C];
__device__ float g_s[KSPLIT][BATCH][C];
__device__ float g_Gt[BATCH][TRIU];     // reduced Gram, triu-linear

// SYRK: 10 super-tiles (2x2 blocks of 16x16 tiles) covering 8x8 upper tri
__constant__ int8_t u_SI[10] = {0,0,0,1,1,2, 0,1,2,3};
__constant__ int8_t u_SJ[10] = {1,2,3,2,3,3, 0,1,2,3};

// NS: 36 upper-tri tiles over 12 warps x 3 slots (sorted by ti for A reuse)
__constant__ int8_t s_TI[12][3] = {
    {0,0,0}, {0,0,0}, {0,0,1}, {1,1,1}, {1,1,1}, {2,2,2},
    {2,2,2}, {3,3,3}, {3,3,4}, {4,4,4}, {5,5,5}, {6,6,7}};
__constant__ int8_t s_TJ[12][3] = {
    {0,1,2}, {3,4,5}, {6,7,1}, {2,3,4}, {5,6,7}, {2,3,4},
    {5,6,7}, {3,4,5}, {6,7,4}, {5,6,7}, {5,6,7}, {6,7,7}};

__device__ __forceinline__ float rtf32(float f) {
    uint32_t u; asm("cvt.rna.tf32.f32 %0, %1;" : "=r"(u) : "f"(f));
    return __uint_as_float(u);
}

// decode linear triu pos -> (i, j)
__device__ __forceinline__ void triu_ij(int pos, int& i, int& j) {
    i = (int)((257.0f - sqrtf(66049.0f - 8.0f * (float)pos)) * 0.5f);
    if (i < 0) i = 0;
    if (i > 127) i = 127;
    while (i > 0 && i * (257 - i) / 2 > pos) i--;
    while (i < 127 && (i + 1) * (257 - (i + 1)) / 2 <= pos) i++;
    j = i + (pos - i * (257 - i) / 2);
}

typedef wmma::fragment<wmma::accumulator, 16, 16, 8, float> AccFrag;
typedef wmma::fragment<wmma::matrix_a, 16, 16, 8, wmma::precision::tf32, wmma::row_major> AFragR;
typedef wmma::fragment<wmma::matrix_a, 16, 16, 8, wmma::precision::tf32, wmma::col_major> AFragC;
typedef wmma::fragment<wmma::matrix_b, 16, 16, 8, wmma::precision::tf32, wmma::row_major> BFragR;

// ===================== Kernel 1: SYRK via wmma tf32 =========================
// grid (KSPLIT, BATCH), 320 threads / 10 warps x 2x2 super-tile.
__global__ __launch_bounds__(SYTHR, 2)
void syrk_tc(const float* __restrict__ x) {
    __shared__ __align__(16) float Xt[2][32 * XTLD];
    const int ks = blockIdx.x, b = blockIdx.y;
    const int t = threadIdx.x, w = t >> 5;
    const float* xb = x + (size_t)b * C * HW + (size_t)ks * KPART;

    const int ti0 = u_SI[w] * 2, tj0 = u_SJ[w] * 2;
    const bool diag = (w >= 6);

    AccFrag acc[4];
#pragma unroll
    for (int s = 0; s < 4; s++) wmma::fill_fragment(acc[s], 0.0f);

    const bool ldr = (t < 256);
    const int r0 = t >> 3, seg = t & 7;     // valid when ldr
    float4 R[4];
    float rs[4] = {0.f, 0.f, 0.f, 0.f};
    if (ldr) {
#pragma unroll
        for (int q = 0; q < 4; q++)
            R[q] = *(const float4*)(xb + (size_t)(r0 + q * 32) * HW + seg * 4);
    }

    for (int c = 0; c < NCHUNK; c++) {
        float* buf = Xt[c & 1];
        if (ldr) {
#pragma unroll
            for (int q = 0; q < 4; q++) {
                const float4 v = R[q];
                rs[q] += v.x + v.y + v.z + v.w;
                const int col = r0 + q * 32;
                buf[(seg * 4 + 0) * XTLD + col] = rtf32(v.x);
                buf[(seg * 4 + 1) * XTLD + col] = rtf32(v.y);
                buf[(seg * 4 + 2) * XTLD + col] = rtf32(v.z);
                buf[(seg * 4 + 3) * XTLD + col] = rtf32(v.w);
            }
            if (c + 1 < NCHUNK) {
                const float* xc = xb + (c + 1) * 32 + seg * 4;
#pragma unroll
                for (int q = 0; q < 4; q++)
                    R[q] = *(const float4*)(xc + (size_t)(r0 + q * 32) * HW);
            }
        }
        __syncthreads();
#pragma unroll
        for (int kk0 = 0; kk0 < 32; kk0 += 8) {
            const float* kbase = buf + kk0 * XTLD;
            AFragC a0, a1; BFragR b0, b1;
            wmma::load_matrix_sync(a0, kbase + ti0 * 16, XTLD);
            wmma::load_matrix_sync(a1, kbase + ti0 * 16 + 16, XTLD);
            wmma::load_matrix_sync(b0, kbase + tj0 * 16, XTLD);
            wmma::load_matrix_sync(b1, kbase + tj0 * 16 + 16, XTLD);
            wmma::mma_sync(acc[0], a0, b0, acc[0]);
            wmma::mma_sync(acc[1], a0, b1, acc[1]);
            if (!diag) wmma::mma_sync(acc[2], a1, b0, acc[2]);
            wmma::mma_sync(acc[3], a1, b1, acc[3]);
        }
    }

    float* Gp = &g_G[ks][b][0][0];
    wmma::store_matrix_sync(Gp + ti0 * 16 * C + tj0 * 16, acc[0], C, wmma::mem_row_major);
    wmma::store_matrix_sync(Gp + ti0 * 16 * C + (tj0 + 1) * 16, acc[1], C, wmma::mem_row_major);
    if (!diag)
        wmma::store_matrix_sync(Gp + (ti0 + 1) * 16 * C + tj0 * 16, acc[2], C, wmma::mem_row_major);
    wmma::store_matrix_sync(Gp + (ti0 + 1) * 16 * C + (tj0 + 1) * 16, acc[3], C, wmma::mem_row_major);

    if (ldr) {
#pragma unroll
        for (int q = 0; q < 4; q++) {
            rs[q] += __shfl_xor_sync(0xffffffffu, rs[q], 1);
            rs[q] += __shfl_xor_sync(0xffffffffu, rs[q], 2);
            rs[q] += __shfl_xor_sync(0xffffffffu, rs[q], 4);
        }
        if (seg == 0) {
#pragma unroll
            for (int q = 0; q < 4; q++) g_s[ks][b][r0 + q * 32] = rs[q];
        }
    }
}

// ===================== Kernel 1b: reduce partials to triu-linear ============
__global__ __launch_bounds__(256)
void reduce_g() {
    const int b = blockIdx.y;
    const int pos = blockIdx.x * 256 + threadIdx.x;
    if (pos >= TRIU) return;
    int i, j;
    triu_ij(pos, i, j);
    float g = 0.f;
#pragma unroll
    for (int p = 0; p < KSPLIT; p++) g += g_G[p][b][i][j];
    g_Gt[b][pos] = g;
}

// ===================== Kernel 2: fused Newton-Schulz ========================
// grid (BATCH), 384 threads / 12 warps x 3 tiles; shared-B phase 2.
#define NS_FLOATS (3 * 128 * MLD + 128 + 16)

__global__ __launch_bounds__(NSTHR, 1)
void ns_tc(float* __restrict__ out) {
    extern __shared__ __align__(16) float sm[];
    float* Y  = sm;
    float* Z  = Y + 128 * MLD;
    float* T  = Z + 128 * MLD;
    float* mu = T + 128 * MLD;
    float* red = mu + 128;

    const int b = blockIdx.x;
    const int t = threadIdx.x, w = t >> 5, lane = t & 31;

    int ti[3], tj[3];
#pragma unroll
    for (int s = 0; s < 3; s++) { ti[s] = s_TI[w][s]; tj[s] = s_TJ[w][s]; }

    // ---- prologue: mean, trace, Y0 = rna(sigma/tr) ----
    const float invn = 1.0f / (float)HW;
    const float* Gt = &g_Gt[b][0];

    if (t < 128) {
        float s = 0.f;
#pragma unroll
        for (int p = 0; p < KSPLIT; p++) s += g_s[p][b][t];
        mu[t] = s * invn;
    }
    __syncthreads();
    float dsum = 0.f;
    if (t < 128) {
        const float g = Gt[t * (257 - t) / 2];   // diag, triu-linear
        const float m = mu[t];
        dsum = g * invn - m * m;
    }
#pragma unroll
    for (int o = 16; o; o >>= 1) dsum += __shfl_down_sync(0xffffffffu, dsum, o);
    if (t < 128 && lane == 0) red[w] = dsum;
    __syncthreads();
    const float tr = red[0] + red[1] + red[2] + red[3];
    const float invtr = 1.0f / tr;

    // Y0 from triu-linear reduced Gram; mirror into smem.
    for (int pos = t; pos < TRIU; pos += NSTHR) {
        int i, j;
        triu_ij(pos, i, j);
        const float g = Gt[pos];
        const float y0 = rtf32((g * invn - mu[i] * mu[j]) * invtr);
        Y[i * MLD + j] = y0;
        Y[j * MLD + i] = y0;
    }
    __syncthreads();

    for (int it = 0; it < NUM_ITER; it++) {
        const bool lastit = (it == NUM_ITER - 1);
        const bool doZ = (it >= 1 && !lastit);

        if (it == 0) {
            // Z0 = I  =>  T0 = rna(1.5I - 0.5 Y0); Z1 = T0
            for (int e = t; e < C * C; e += NSTHR) {
                const int i = e >> 7, j = e & 127;
                const float v = rtf32(fmaf(-0.5f, Y[i * MLD + j], (i == j) ? 1.5f : 0.0f));
                T[i * MLD + j] = v;
                Z[i * MLD + j] = v;
            }
            __syncthreads();
        } else {
            // ---- phase 1: T = rna(-0.5 * (Z @ Y)), then diag += 1.5 ----
            AccFrag a1[3];
#pragma unroll
            for (int s = 0; s < 3; s++) wmma::fill_fragment(a1[s], 0.0f);
#pragma unroll 4
            for (int k0 = 0; k0 < C; k0 += 8) {
                AFragR az; BFragR by;
#pragma unroll
                for (int s = 0; s < 3; s++) {
                    if (s == 0 || ti[s] != ti[s - 1])
                        wmma::load_matrix_sync(az, Z + ti[s] * 16 * MLD + k0, MLD);
                    wmma::load_matrix_sync(by, Y + k0 * MLD + tj[s] * 16, MLD);
                    wmma::mma_sync(a1[s], az, by, a1[s]);
                }
            }
#pragma unroll
            for (int s = 0; s < 3; s++) {
#pragma unroll
                for (int e = 0; e < a1[s].num_elements; e++)
                    a1[s].x[e] = rtf32(-0.5f * a1[s].x[e]);
                wmma::store_matrix_sync(T + ti[s] * 16 * MLD + tj[s] * 16, a1[s], MLD, wmma::mem_row_major);
                if (tj[s] > ti[s])
                    wmma::store_matrix_sync(T + tj[s] * 16 * MLD + ti[s] * 16, a1[s], MLD, wmma::mem_col_major);
            }
            __syncthreads();
            if (t < 128) T[t * MLD + t] = rtf32(1.5f + T[t * MLD + t]);
            __syncthreads();
        }

        // ---- phase 2: Ynew = Y@T ; Znew = sym(Z@T) -- shared B fragment ----
        {
            AccFrag a2[3], a3[3];
#pragma unroll
            for (int s = 0; s < 3; s++) { wmma::fill_fragment(a2[s], 0.0f); wmma::fill_fragment(a3[s], 0.0f); }
#pragma unroll 4
            for (int k0 = 0; k0 < C; k0 += 8) {
                AFragR ay, az; BFragR bt;
#pragma unroll
                for (int s = 0; s < 3; s++) {
                    if (s == 0 || ti[s] != ti[s - 1]) {
                        wmma::load_matrix_sync(ay, Y + ti[s] * 16 * MLD + k0, MLD);
                        if (doZ)
                            wmma::load_matrix_sync(az, Z + ti[s] * 16 * MLD + k0, MLD);
                    }
                    wmma::load_matrix_sync(bt, T + k0 * MLD + tj[s] * 16, MLD);
                    wmma::mma_sync(a2[s], ay, bt, a2[s]);
                    if (doZ)
                        wmma::mma_sync(a3[s], az, bt, a3[s]);
                }
            }
            __syncthreads();   // all reads of Y/Z complete before overwrite
            if (!lastit) {
#pragma unroll
                for (int s = 0; s < 3; s++)
#pragma unroll
                    for (int e = 0; e < a2[s].num_elements; e++) {
                        a2[s].x[e] = rtf32(a2[s].x[e]);
                        a3[s].x[e] = rtf32(a3[s].x[e]);
                    }
            }
#pragma unroll
            for (int s = 0; s < 3; s++) {
                wmma::store_matrix_sync(Y + ti[s] * 16 * MLD + tj[s] * 16, a2[s], MLD, wmma::mem_row_major);
                if (tj[s] > ti[s])
                    wmma::store_matrix_sync(Y + tj[s] * 16 * MLD + ti[s] * 16, a2[s], MLD, wmma::mem_col_major);
                if (doZ) {
                    wmma::store_matrix_sync(Z + ti[s] * 16 * MLD + tj[s] * 16, a3[s], MLD, wmma::mem_row_major);
                    if (tj[s] > ti[s])
                        wmma::store_matrix_sync(Z + tj[s] * 16 * MLD + ti[s] * 16, a3[s], MLD, wmma::mem_col_major);
                }
            }
        }
        __syncthreads();
    }

    // ---- output: triu(Y * sqrt(tr)) ----
    const float s = sqrtf(tr);
    if (t < 128) {
        const int i = t;
        float* o = out + (size_t)b * TRIU + i * (257 - i) / 2;
        const float* yr = Y + i * MLD;
        for (int j = i; j < C; j++) o[j - i] = yr[j] * s;
    }
}

// =================== launch ==================================================
extern "C" void kernel_launch(void* const* d_in, const int* in_sizes, int n_in,
                              void* d_out, int out_size) {
    const float* x = (const float*)d_in[0];
    float* out = (float*)d_out;
    cudaFuncSetAttribute(ns_tc, cudaFuncAttributeMaxDynamicSharedMemorySize,
                         NS_FLOATS * (int)sizeof(float));
    dim3 g1(KSPLIT, BATCH);
    syrk_tc<<<g1, SYTHR>>>(x);
    dim3 g2(33, BATCH);
    reduce_g<<<g2, 256>>>();
    ns_tc<<<BATCH, NSTHR, NS_FLOATS * sizeof(float)>>>(out);
}